// round 8
// baseline (speedup 1.0000x reference)
#include <cuda_runtime.h>
#include <cuda_fp16.h>
#include <math.h>
#include <stdint.h>

// ---------------- Problem constants ----------------
#define NN    30000
#define EE    480000
#define ETOT  (EE + NN)
#define FIN   4096
#define D1    512
#define H1    4
#define C1    128
#define CLS   6
#define SLOPE 0.2f

// ---------------- Device scratch ----------------
__device__ __half g_h1h[(size_t)NN * D1];   // layer-1 linear output, fp16
__device__ float g_asrc1[NN * H1];
__device__ float g_adst1[NN * H1];
__device__ float g_h2[NN * CLS];
__device__ float g_as2[NN];
__device__ float g_ad2[NN];
__device__ int   g_deg[NN];
__device__ int   g_off[NN + 1];
__device__ int   g_cur[NN];
__device__ int   g_srcs[ETOT];

// fp16 W1 transposed: [N=512][K=4096]
__device__ __half g_w1t[(size_t)D1 * FIN];

__device__ __forceinline__ float lrelu(float v) { return v > 0.0f ? v : SLOPE * v; }

// ==================== helpers ====================
__device__ __forceinline__ uint32_t smem_u32(const void* p) {
    uint32_t a;
    asm("{ .reg .u64 t; cvta.to.shared.u64 t, %1; cvt.u32.u64 %0, t; }" : "=r"(a) : "l"(p));
    return a;
}

__device__ __forceinline__ void cpa16(uint32_t dst, const void* src) {
    asm volatile("cp.async.cg.shared.global [%0], [%1], 16;\n"
                 :: "r"(dst), "l"(src) : "memory");
}

__device__ __forceinline__ void ldm_x4(uint32_t addr, uint32_t& r0, uint32_t& r1,
                                       uint32_t& r2, uint32_t& r3) {
    asm volatile("ldmatrix.sync.aligned.m8n8.x4.shared.b16 {%0,%1,%2,%3}, [%4];"
                 : "=r"(r0), "=r"(r1), "=r"(r2), "=r"(r3) : "r"(addr));
}

__device__ __forceinline__ void mma_f16(float& d0, float& d1, float& d2, float& d3,
                                        uint32_t a0, uint32_t a1, uint32_t a2, uint32_t a3,
                                        uint32_t b0, uint32_t b1) {
    asm volatile("mma.sync.aligned.m16n8k16.row.col.f32.f16.f16.f32 "
                 "{%0,%1,%2,%3}, {%4,%5,%6,%7}, {%8,%9}, {%0,%1,%2,%3};"
                 : "+f"(d0), "+f"(d1), "+f"(d2), "+f"(d3)
                 : "r"(a0), "r"(a1), "r"(a2), "r"(a3), "r"(b0), "r"(b1));
}

__device__ __forceinline__ uint32_t pack_h2(float a, float b) {
    __half2 h = __halves2half2(__float2half_rn(a), __float2half_rn(b));
    return *(uint32_t*)&h;
}

// ==================== W1 -> fp16 transposed (32x32 tile) ====================
__global__ __launch_bounds__(256) void convw1_kernel(const float* __restrict__ W1) {
    __shared__ float tile[32][33];
    const int kb = blockIdx.y * 32;
    const int nb = blockIdx.x * 32;
    const int t = threadIdx.x;
    const int r = t >> 5, c = t & 31;
#pragma unroll
    for (int rr = r; rr < 32; rr += 8)
        tile[rr][c] = W1[(size_t)(kb + rr) * D1 + nb + c];
    __syncthreads();
#pragma unroll
    for (int rr = r; rr < 32; rr += 8) {
        float v = tile[c][rr];
        g_w1t[(size_t)(nb + rr) * FIN + kb + c] = __float2half_rn(v);
    }
}

// ==================== GEMM1: fused-convert fp16 mma.sync, 128x256 tile ====================
#define BK       32
#define CHUNKS   (FIN / BK)      // 128
#define TILE_A_B (128 * 80)      // 10240
#define TILE_B_B (256 * 80)      // 20480
#define OFF_A    0
#define OFF_B    (TILE_A_B)
#define STAGE_B  (TILE_A_B + TILE_B_B)   // 30720
#define SMEM_SZ  (2 * STAGE_B)           // 61440

__global__ __launch_bounds__(256) void mma1_kernel(const float* __restrict__ x) {
    extern __shared__ __align__(16) char dsm[];
    const uint32_t sb = smem_u32(dsm);

    const int tid = threadIdx.x;
    const int wid = tid >> 5;
    const int lane = tid & 31;
    const int warp_m = wid >> 2;    // 0..1
    const int warp_n = wid & 3;     // 0..3
    const int block_row = blockIdx.y * 128;
    const int nbase = blockIdx.x * 256;

    const int a_r = tid >> 1;
    const int a_half = tid & 1;
    const bool a_ok = (block_row + a_r) < NN;
    const float* a_src = x + (size_t)(block_row + a_r) * FIN + a_half * 16;
    const uint32_t a_dso = (uint32_t)(a_r * 80 + a_half * 32);

    float4 xr[4];
    auto ldA = [&](int c) {
        if (a_ok) {
            const float4* p = (const float4*)(a_src + c * BK);
#pragma unroll
            for (int q = 0; q < 4; q++) xr[q] = p[q];
        } else {
            float4 z = make_float4(0.f, 0.f, 0.f, 0.f);
#pragma unroll
            for (int q = 0; q < 4; q++) xr[q] = z;
        }
    };
    auto stsA = [&](int s) {
        const uint32_t base = sb + s * STAGE_B;
        uint4 h0, h1;
        h0.x = pack_h2(xr[0].x, xr[0].y); h0.y = pack_h2(xr[0].z, xr[0].w);
        h0.z = pack_h2(xr[1].x, xr[1].y); h0.w = pack_h2(xr[1].z, xr[1].w);
        h1.x = pack_h2(xr[2].x, xr[2].y); h1.y = pack_h2(xr[2].z, xr[2].w);
        h1.z = pack_h2(xr[3].x, xr[3].y); h1.w = pack_h2(xr[3].z, xr[3].w);
        uint32_t ah = base + OFF_A + a_dso;
        asm volatile("st.shared.v4.b32 [%0], {%1,%2,%3,%4};" :: "r"(ah), "r"(h0.x), "r"(h0.y), "r"(h0.z), "r"(h0.w));
        asm volatile("st.shared.v4.b32 [%0], {%1,%2,%3,%4};" :: "r"(ah + 16), "r"(h1.x), "r"(h1.y), "r"(h1.z), "r"(h1.w));
    };

    auto cpB = [&](int c, int s) {
        const uint32_t base = sb + s * STAGE_B;
        const int kbase = c * BK;
#pragma unroll
        for (int i = tid; i < 1024; i += 256) {
            int r = i >> 2, q = i & 3;
            uint32_t dso = (uint32_t)(r * 80 + q * 16);
            size_t se = (size_t)(nbase + r) * FIN + kbase + q * 8;
            cpa16(base + OFF_B + dso, g_w1t + se);
        }
    };

    const uint32_t a_off = (uint32_t)((warp_m * 64 + (lane & 15)) * 80 + (lane >> 4) * 16);
    const uint32_t b_off = (uint32_t)((warp_n * 64 + (lane & 7) + ((lane >> 4) << 3)) * 80 +
                                      ((lane >> 3) & 1) * 16);

    float acc[4][8][4];
#pragma unroll
    for (int i = 0; i < 4; i++)
#pragma unroll
        for (int j = 0; j < 8; j++)
#pragma unroll
            for (int q = 0; q < 4; q++) acc[i][j][q] = 0.0f;

    ldA(0);
    stsA(0);
    cpB(0, 0);
    asm volatile("cp.async.commit_group;\n" ::: "memory");
    ldA(1);

    for (int c = 0; c < CHUNKS; c++) {
        const int s = c & 1;
        asm volatile("cp.async.wait_group 0;\n" ::: "memory");
        __syncthreads();

        if (c + 1 < CHUNKS) {
            stsA(s ^ 1);
            cpB(c + 1, s ^ 1);
            asm volatile("cp.async.commit_group;\n" ::: "memory");
        }
        if (c + 2 < CHUNKS) ldA(c + 2);

        const uint32_t stg = sb + s * STAGE_B;
        const uint32_t a_base = stg + OFF_A + a_off;
        const uint32_t b_base = stg + OFF_B + b_off;

#pragma unroll
        for (int kk = 0; kk < 2; kk++) {
            uint32_t av[4][4];
#pragma unroll
            for (int i = 0; i < 4; i++) {
                uint32_t ao = (uint32_t)(i * 16 * 80 + kk * 32);
                ldm_x4(a_base + ao, av[i][0], av[i][1], av[i][2], av[i][3]);
            }
#pragma unroll
            for (int j2 = 0; j2 < 4; j2++) {
                uint32_t b0, b1, b2, b3;
                uint32_t bo = (uint32_t)(j2 * 16 * 80 + kk * 32);
                ldm_x4(b_base + bo, b0, b1, b2, b3);
#pragma unroll
                for (int i = 0; i < 4; i++) {
                    float* d0 = acc[i][2 * j2];
                    float* d1 = acc[i][2 * j2 + 1];
                    mma_f16(d0[0], d0[1], d0[2], d0[3],
                            av[i][0], av[i][1], av[i][2], av[i][3], b0, b1);
                    mma_f16(d1[0], d1[1], d1[2], d1[3],
                            av[i][0], av[i][1], av[i][2], av[i][3], b2, b3);
                }
            }
        }
    }

    // epilogue: write fp16 h1
#pragma unroll
    for (int i = 0; i < 4; i++) {
        int row0 = block_row + warp_m * 64 + i * 16 + (lane >> 2);
#pragma unroll
        for (int j = 0; j < 8; j++) {
            int col = nbase + warp_n * 64 + j * 8 + (lane & 3) * 2;
            if (row0 < NN)
                *(uint32_t*)(g_h1h + (size_t)row0 * D1 + col) = pack_h2(acc[i][j][0], acc[i][j][1]);
            if (row0 + 8 < NN)
                *(uint32_t*)(g_h1h + (size_t)(row0 + 8) * D1 + col) = pack_h2(acc[i][j][2], acc[i][j][3]);
        }
    }
}

// ==================== CSR build ====================
__global__ void zero_deg_kernel() {
    int i = blockIdx.x * blockDim.x + threadIdx.x;
    if (i < NN) g_deg[i] = 0;
}

__global__ void count_kernel(const int* __restrict__ ei) {
    int e = blockIdx.x * blockDim.x + threadIdx.x;
    if (e >= ETOT) return;
    int dst = (e < EE) ? ei[EE + e] : (e - EE);
    atomicAdd(&g_deg[dst], 1);
}

__global__ __launch_bounds__(1024) void scan_kernel() {
    __shared__ int part[1024];
    const int t = threadIdx.x;
    const int CH = (NN + 1023) / 1024;
    const int base = t * CH;
    int s = 0;
    for (int i = 0; i < CH; i++) {
        int idx = base + i;
        if (idx < NN) s += g_deg[idx];
    }
    part[t] = s;
    __syncthreads();
    for (int o = 1; o < 1024; o <<= 1) {
        int v = (t >= o) ? part[t - o] : 0;
        __syncthreads();
        part[t] += v;
        __syncthreads();
    }
    int run = part[t] - s;
    for (int i = 0; i < CH; i++) {
        int idx = base + i;
        if (idx < NN) {
            g_off[idx] = run;
            g_cur[idx] = run;
            run += g_deg[idx];
        }
    }
    if (t == 1023) g_off[NN] = part[1023];
}

__global__ void scatter_kernel(const int* __restrict__ ei) {
    int e = blockIdx.x * blockDim.x + threadIdx.x;
    if (e >= ETOT) return;
    int src, dst;
    if (e < EE) { src = ei[e]; dst = ei[EE + e]; }
    else        { src = e - EE; dst = e - EE; }
    int pos = atomicAdd(&g_cur[dst], 1);
    g_srcs[pos] = src;
}

// ==================== Layer 1 alphas (fp16 h1) ====================
__global__ void alpha1_kernel(const float* __restrict__ a_s, const float* __restrict__ a_d) {
    int warp = blockIdx.x * 8 + (threadIdx.x >> 5);
    int lane = threadIdx.x & 31;
    if (warp >= NN) return;
    const __half2* row2 = (const __half2*)(g_h1h + (size_t)warp * D1);
#pragma unroll
    for (int h = 0; h < H1; h++) {
        float ss = 0.f, sd = 0.f;
#pragma unroll
        for (int k = 0; k < 2; k++) {
            int p = h * 64 + lane + 32 * k;
            float2 v = __half22float2(row2[p]);
            int c = 2 * p;
            ss = fmaf(v.x, a_s[c], ss);     ss = fmaf(v.y, a_s[c + 1], ss);
            sd = fmaf(v.x, a_d[c], sd);     sd = fmaf(v.y, a_d[c + 1], sd);
        }
#pragma unroll
        for (int o = 16; o; o >>= 1) {
            ss += __shfl_xor_sync(0xffffffffu, ss, o);
            sd += __shfl_xor_sync(0xffffffffu, sd, o);
        }
        if (lane == 0) {
            g_asrc1[warp * H1 + h] = ss;
            g_adst1[warp * H1 + h] = sd;
        }
    }
}

// ==================== Fused: softmax+aggregate+ELU + gemm2 + alpha2 ====================
__global__ __launch_bounds__(128) void agg1_kernel(const float* __restrict__ b1,
                                                   const float* __restrict__ W2,
                                                   const float* __restrict__ as2w,
                                                   const float* __restrict__ ad2w) {
    const int n = blockIdx.x;
    const int t = threadIdx.x;
    const int h = t >> 5;
    const int lane = t & 31;
    const int s0 = g_off[n];
    const int deg = g_off[n + 1] - s0;

    __shared__ float adsts[H1];
    __shared__ float sm[H1];
    __shared__ float sinv[H1];
    __shared__ float red[128 * H1];
    __shared__ int   ssrc[128];
    __shared__ float scoef[128 * H1];

    if (t < H1) adsts[t] = g_adst1[n * H1 + t];
    __syncthreads();

    const float4* asrc4 = (const float4*)g_asrc1;

    float lm[H1] = {-INFINITY, -INFINITY, -INFINITY, -INFINITY};
    for (int i = t; i < deg; i += 128) {
        float4 as = asrc4[g_srcs[s0 + i]];
        lm[0] = fmaxf(lm[0], lrelu(as.x + adsts[0]));
        lm[1] = fmaxf(lm[1], lrelu(as.y + adsts[1]));
        lm[2] = fmaxf(lm[2], lrelu(as.z + adsts[2]));
        lm[3] = fmaxf(lm[3], lrelu(as.w + adsts[3]));
    }
#pragma unroll
    for (int hh = 0; hh < H1; hh++) red[t * H1 + hh] = lm[hh];
    __syncthreads();
    if (t < H1) {
        float m = -INFINITY;
        for (int i = 0; i < 128; i++) m = fmaxf(m, red[i * H1 + t]);
        sm[t] = m;
    }
    __syncthreads();

    float ls[H1] = {0.f, 0.f, 0.f, 0.f};
    for (int i = t; i < deg; i += 128) {
        float4 as = asrc4[g_srcs[s0 + i]];
        ls[0] += expf(lrelu(as.x + adsts[0]) - sm[0]);
        ls[1] += expf(lrelu(as.y + adsts[1]) - sm[1]);
        ls[2] += expf(lrelu(as.z + adsts[2]) - sm[2]);
        ls[3] += expf(lrelu(as.w + adsts[3]) - sm[3]);
    }
#pragma unroll
    for (int hh = 0; hh < H1; hh++) red[t * H1 + hh] = ls[hh];
    __syncthreads();
    if (t < H1) {
        float s = 0.f;
        for (int i = 0; i < 128; i++) s += red[i * H1 + t];
        sinv[t] = 1.0f / s;
    }
    __syncthreads();

    // phase 3: thread t owns channels [4t, 4t+4)
    float ax = 0.f, ay = 0.f, az = 0.f, aw = 0.f;
    for (int base = 0; base < deg; base += 128) {
        int cnt = min(128, deg - base);
        if (t < cnt) {
            int s = g_srcs[s0 + base + t];
            ssrc[t] = s;
            float4 as = asrc4[s];
            scoef[t * H1 + 0] = expf(lrelu(as.x + adsts[0]) - sm[0]) * sinv[0];
            scoef[t * H1 + 1] = expf(lrelu(as.y + adsts[1]) - sm[1]) * sinv[1];
            scoef[t * H1 + 2] = expf(lrelu(as.z + adsts[2]) - sm[2]) * sinv[2];
            scoef[t * H1 + 3] = expf(lrelu(as.w + adsts[3]) - sm[3]) * sinv[3];
        }
        __syncthreads();
        int i = 0;
        for (; i + 2 <= cnt; i += 2) {
            int sA = ssrc[i], sB = ssrc[i + 1];
            uint2 uA = *(const uint2*)(g_h1h + (size_t)sA * D1 + 4 * t);
            uint2 uB = *(const uint2*)(g_h1h + (size_t)sB * D1 + 4 * t);
            float2 a0 = __half22float2(*(__half2*)&uA.x);
            float2 a1 = __half22float2(*(__half2*)&uA.y);
            float2 b0 = __half22float2(*(__half2*)&uB.x);
            float2 b1 = __half22float2(*(__half2*)&uB.y);
            float cA = scoef[i * H1 + h];
            float cB = scoef[(i + 1) * H1 + h];
            ax = fmaf(cA, a0.x, ax); ay = fmaf(cA, a0.y, ay);
            az = fmaf(cA, a1.x, az); aw = fmaf(cA, a1.y, aw);
            ax = fmaf(cB, b0.x, ax); ay = fmaf(cB, b0.y, ay);
            az = fmaf(cB, b1.x, az); aw = fmaf(cB, b1.y, aw);
        }
        if (i < cnt) {
            uint2 u = *(const uint2*)(g_h1h + (size_t)ssrc[i] * D1 + 4 * t);
            float2 v0 = __half22float2(*(__half2*)&u.x);
            float2 v1 = __half22float2(*(__half2*)&u.y);
            float cf = scoef[i * H1 + h];
            ax = fmaf(cf, v0.x, ax); ay = fmaf(cf, v0.y, ay);
            az = fmaf(cf, v1.x, az); aw = fmaf(cf, v1.y, aw);
        }
        __syncthreads();
    }

    // bias + ELU in registers
    float4 bb = *(const float4*)(b1 + 4 * t);
    float ox = ax + bb.x; ox = ox > 0.f ? ox : expm1f(ox);
    float oy = ay + bb.y; oy = oy > 0.f ? oy : expm1f(oy);
    float oz = az + bb.z; oz = oz > 0.f ? oz : expm1f(oz);
    float ow = aw + bb.w; ow = ow > 0.f ? ow : expm1f(ow);

    // fused gemm2: p[c] = sum over this thread's 4 channels of o*W2[ch][c]
    float p[CLS];
    {
        const float* w0 = W2 + (size_t)(4 * t) * CLS;
#pragma unroll
        for (int c = 0; c < CLS; c++)
            p[c] = ox * w0[c] + oy * w0[CLS + c] + oz * w0[2 * CLS + c] + ow * w0[3 * CLS + c];
    }
    // warp reduce
#pragma unroll
    for (int o = 16; o; o >>= 1)
#pragma unroll
        for (int c = 0; c < CLS; c++) p[c] += __shfl_xor_sync(0xffffffffu, p[c], o);
    if (lane == 0) {
#pragma unroll
        for (int c = 0; c < CLS; c++) red[h * CLS + c] = p[c];
    }
    __syncthreads();
    if (t == 0) {
        float h2v[CLS];
        float s2 = 0.f, d2 = 0.f;
#pragma unroll
        for (int c = 0; c < CLS; c++) {
            float v = red[c] + red[CLS + c] + red[2 * CLS + c] + red[3 * CLS + c];
            h2v[c] = v;
            s2 = fmaf(v, as2w[c], s2);
            d2 = fmaf(v, ad2w[c], d2);
        }
#pragma unroll
        for (int c = 0; c < CLS; c++) g_h2[n * CLS + c] = h2v[c];
        g_as2[n] = s2;
        g_ad2[n] = d2;
    }
}

// ==================== Layer 2 aggregation ====================
__global__ __launch_bounds__(128) void agg2_kernel(const float* __restrict__ b2,
                                                   float* __restrict__ out) {
    int n = blockIdx.x * 4 + (threadIdx.x >> 5);
    int lane = threadIdx.x & 31;
    if (n >= NN) return;
    int s0 = g_off[n];
    int deg = g_off[n + 1] - s0;
    float ad = g_ad2[n];

    float lmax = -INFINITY;
    for (int i = lane; i < deg; i += 32) {
        int s = g_srcs[s0 + i];
        lmax = fmaxf(lmax, lrelu(g_as2[s] + ad));
    }
#pragma unroll
    for (int o = 16; o; o >>= 1) lmax = fmaxf(lmax, __shfl_xor_sync(0xffffffffu, lmax, o));

    float lsum = 0.f;
    for (int i = lane; i < deg; i += 32) {
        int s = g_srcs[s0 + i];
        lsum += expf(lrelu(g_as2[s] + ad) - lmax);
    }
#pragma unroll
    for (int o = 16; o; o >>= 1) lsum += __shfl_xor_sync(0xffffffffu, lsum, o);
    float inv = 1.0f / lsum;

    float acc[CLS] = {0.f, 0.f, 0.f, 0.f, 0.f, 0.f};
    for (int i = lane; i < deg; i += 32) {
        int s = g_srcs[s0 + i];
        float coef = expf(lrelu(g_as2[s] + ad) - lmax) * inv;
        const float* hp = g_h2 + s * CLS;
#pragma unroll
        for (int c = 0; c < CLS; c++) acc[c] = fmaf(coef, hp[c], acc[c]);
    }
#pragma unroll
    for (int o = 16; o; o >>= 1)
#pragma unroll
        for (int c = 0; c < CLS; c++) acc[c] += __shfl_xor_sync(0xffffffffu, acc[c], o);

    if (lane == 0) {
#pragma unroll
        for (int c = 0; c < CLS; c++) out[n * CLS + c] = acc[c] + b2[c];
    }
}

// ==================== Launch ====================
extern "C" void kernel_launch(void* const* d_in, const int* in_sizes, int n_in,
                              void* d_out, int out_size) {
    const float* x   = (const float*)d_in[0];
    const int*   ei  = (const int*)  d_in[1];
    const float* W1  = (const float*)d_in[2];
    const float* as1 = (const float*)d_in[3];
    const float* ad1 = (const float*)d_in[4];
    const float* b1  = (const float*)d_in[5];
    const float* W2  = (const float*)d_in[6];
    const float* as2 = (const float*)d_in[7];
    const float* ad2 = (const float*)d_in[8];
    const float* b2  = (const float*)d_in[9];
    float* out = (float*)d_out;

    static bool attr_set = false;
    if (!attr_set) {
        cudaFuncSetAttribute(mma1_kernel, cudaFuncAttributeMaxDynamicSharedMemorySize, SMEM_SZ);
        attr_set = true;
    }

    // CSR build
    zero_deg_kernel<<<(NN + 255) / 256, 256>>>();
    count_kernel<<<(ETOT + 255) / 256, 256>>>(ei);
    scan_kernel<<<1, 1024>>>();
    scatter_kernel<<<(ETOT + 255) / 256, 256>>>(ei);

    // W1 -> fp16 transposed
    convw1_kernel<<<dim3(D1 / 32, FIN / 32), 256>>>(W1);

    // Layer 1
    mma1_kernel<<<dim3(D1 / 256, (NN + 127) / 128), 256, SMEM_SZ>>>(x);
    alpha1_kernel<<<(NN + 7) / 8, 256>>>(as1, ad1);
    // Fused agg1 + gemm2 + alpha2
    agg1_kernel<<<NN, 128>>>(b1, W2, as2, ad2);

    // Layer 2 aggregation
    agg2_kernel<<<(NN + 3) / 4, 128>>>(b2, out);
}

// round 9
// speedup vs baseline: 1.0319x; 1.0319x over previous
#include <cuda_runtime.h>
#include <cuda_fp16.h>
#include <math.h>
#include <stdint.h>

// ---------------- Problem constants ----------------
#define NN    30000
#define EE    480000
#define ETOT  (EE + NN)
#define FIN   4096
#define D1    512
#define H1    4
#define C1    128
#define CLS   6
#define SLOPE 0.2f
#define NEGBIG (-3.402823466e38f)

// ---------------- Device scratch ----------------
__device__ __half g_h1h[(size_t)NN * D1];   // layer-1 linear output, fp16
__device__ float g_out1[(size_t)NN * D1];   // post-attention + ELU (fp32)
__device__ float g_asrc1[NN * H1];
__device__ float g_adst1[NN * H1];
__device__ float g_h2[NN * CLS];
__device__ float g_as2[NN];
__device__ float g_ad2[NN];
__device__ int   g_deg[NN];
__device__ int   g_off[NN + 1];
__device__ int   g_cur[NN];
__device__ int   g_srcs[ETOT];

// fp16 W1 transposed: [N=512][K=4096]
__device__ __half g_w1t[(size_t)D1 * FIN];

__device__ __forceinline__ float lrelu(float v) { return v > 0.0f ? v : SLOPE * v; }

// ==================== helpers ====================
__device__ __forceinline__ uint32_t smem_u32(const void* p) {
    uint32_t a;
    asm("{ .reg .u64 t; cvta.to.shared.u64 t, %1; cvt.u32.u64 %0, t; }" : "=r"(a) : "l"(p));
    return a;
}

__device__ __forceinline__ void cpa16(uint32_t dst, const void* src) {
    asm volatile("cp.async.cg.shared.global [%0], [%1], 16;\n"
                 :: "r"(dst), "l"(src) : "memory");
}

__device__ __forceinline__ void ldm_x4(uint32_t addr, uint32_t& r0, uint32_t& r1,
                                       uint32_t& r2, uint32_t& r3) {
    asm volatile("ldmatrix.sync.aligned.m8n8.x4.shared.b16 {%0,%1,%2,%3}, [%4];"
                 : "=r"(r0), "=r"(r1), "=r"(r2), "=r"(r3) : "r"(addr));
}

__device__ __forceinline__ void mma_f16(float& d0, float& d1, float& d2, float& d3,
                                        uint32_t a0, uint32_t a1, uint32_t a2, uint32_t a3,
                                        uint32_t b0, uint32_t b1) {
    asm volatile("mma.sync.aligned.m16n8k16.row.col.f32.f16.f16.f32 "
                 "{%0,%1,%2,%3}, {%4,%5,%6,%7}, {%8,%9}, {%0,%1,%2,%3};"
                 : "+f"(d0), "+f"(d1), "+f"(d2), "+f"(d3)
                 : "r"(a0), "r"(a1), "r"(a2), "r"(a3), "r"(b0), "r"(b1));
}

__device__ __forceinline__ uint32_t pack_h2(float a, float b) {
    __half2 h = __halves2half2(__float2half_rn(a), __float2half_rn(b));
    return *(uint32_t*)&h;
}

// ==================== W1 -> fp16 transposed (32x32 tile) ====================
__global__ __launch_bounds__(256) void convw1_kernel(const float* __restrict__ W1) {
    __shared__ float tile[32][33];
    const int kb = blockIdx.y * 32;
    const int nb = blockIdx.x * 32;
    const int t = threadIdx.x;
    const int r = t >> 5, c = t & 31;
#pragma unroll
    for (int rr = r; rr < 32; rr += 8)
        tile[rr][c] = W1[(size_t)(kb + rr) * D1 + nb + c];
    __syncthreads();
#pragma unroll
    for (int rr = r; rr < 32; rr += 8) {
        float v = tile[c][rr];
        g_w1t[(size_t)(nb + rr) * FIN + kb + c] = __float2half_rn(v);
    }
}

// ==================== GEMM1 + fused alpha1: fp16 mma.sync, 128x256 tile ====================
#define BK       32
#define CHUNKS   (FIN / BK)      // 128
#define TILE_A_B (128 * 80)      // 10240
#define TILE_B_B (256 * 80)      // 20480
#define OFF_A    0
#define OFF_B    (TILE_A_B)
#define STAGE_B  (TILE_A_B + TILE_B_B)   // 30720
#define SMEM_SZ  (2 * STAGE_B)           // 61440

__global__ __launch_bounds__(256) void mma1_kernel(const float* __restrict__ x,
                                                   const float* __restrict__ a_s,
                                                   const float* __restrict__ a_d) {
    extern __shared__ __align__(16) char dsm[];
    const uint32_t sb = smem_u32(dsm);

    const int tid = threadIdx.x;
    const int wid = tid >> 5;
    const int lane = tid & 31;
    const int warp_m = wid >> 2;    // 0..1
    const int warp_n = wid & 3;     // 0..3
    const int block_row = blockIdx.y * 128;
    const int nbase = blockIdx.x * 256;

    const int a_r = tid >> 1;
    const int a_half = tid & 1;
    const bool a_ok = (block_row + a_r) < NN;
    const float* a_src = x + (size_t)(block_row + a_r) * FIN + a_half * 16;
    const uint32_t a_dso = (uint32_t)(a_r * 80 + a_half * 32);

    float4 xr[4];
    auto ldA = [&](int c) {
        if (a_ok) {
            const float4* p = (const float4*)(a_src + c * BK);
#pragma unroll
            for (int q = 0; q < 4; q++) xr[q] = p[q];
        } else {
            float4 z = make_float4(0.f, 0.f, 0.f, 0.f);
#pragma unroll
            for (int q = 0; q < 4; q++) xr[q] = z;
        }
    };
    auto stsA = [&](int s) {
        const uint32_t base = sb + s * STAGE_B;
        uint4 h0, h1;
        h0.x = pack_h2(xr[0].x, xr[0].y); h0.y = pack_h2(xr[0].z, xr[0].w);
        h0.z = pack_h2(xr[1].x, xr[1].y); h0.w = pack_h2(xr[1].z, xr[1].w);
        h1.x = pack_h2(xr[2].x, xr[2].y); h1.y = pack_h2(xr[2].z, xr[2].w);
        h1.z = pack_h2(xr[3].x, xr[3].y); h1.w = pack_h2(xr[3].z, xr[3].w);
        uint32_t ah = base + OFF_A + a_dso;
        asm volatile("st.shared.v4.b32 [%0], {%1,%2,%3,%4};" :: "r"(ah), "r"(h0.x), "r"(h0.y), "r"(h0.z), "r"(h0.w));
        asm volatile("st.shared.v4.b32 [%0], {%1,%2,%3,%4};" :: "r"(ah + 16), "r"(h1.x), "r"(h1.y), "r"(h1.z), "r"(h1.w));
    };

    auto cpB = [&](int c, int s) {
        const uint32_t base = sb + s * STAGE_B;
        const int kbase = c * BK;
#pragma unroll
        for (int i = tid; i < 1024; i += 256) {
            int r = i >> 2, q = i & 3;
            uint32_t dso = (uint32_t)(r * 80 + q * 16);
            size_t se = (size_t)(nbase + r) * FIN + kbase + q * 8;
            cpa16(base + OFF_B + dso, g_w1t + se);
        }
    };

    const uint32_t a_off = (uint32_t)((warp_m * 64 + (lane & 15)) * 80 + (lane >> 4) * 16);
    const uint32_t b_off = (uint32_t)((warp_n * 64 + (lane & 7) + ((lane >> 4) << 3)) * 80 +
                                      ((lane >> 3) & 1) * 16);

    float acc[4][8][4];
#pragma unroll
    for (int i = 0; i < 4; i++)
#pragma unroll
        for (int j = 0; j < 8; j++)
#pragma unroll
            for (int q = 0; q < 4; q++) acc[i][j][q] = 0.0f;

    ldA(0);
    stsA(0);
    cpB(0, 0);
    asm volatile("cp.async.commit_group;\n" ::: "memory");
    ldA(1);

    for (int c = 0; c < CHUNKS; c++) {
        const int s = c & 1;
        asm volatile("cp.async.wait_group 0;\n" ::: "memory");
        __syncthreads();

        if (c + 1 < CHUNKS) {
            stsA(s ^ 1);
            cpB(c + 1, s ^ 1);
            asm volatile("cp.async.commit_group;\n" ::: "memory");
        }
        if (c + 2 < CHUNKS) ldA(c + 2);

        const uint32_t stg = sb + s * STAGE_B;
        const uint32_t a_base = stg + OFF_A + a_off;
        const uint32_t b_base = stg + OFF_B + b_off;

#pragma unroll
        for (int kk = 0; kk < 2; kk++) {
            uint32_t av[4][4];
#pragma unroll
            for (int i = 0; i < 4; i++) {
                uint32_t ao = (uint32_t)(i * 16 * 80 + kk * 32);
                ldm_x4(a_base + ao, av[i][0], av[i][1], av[i][2], av[i][3]);
            }
#pragma unroll
            for (int j2 = 0; j2 < 4; j2++) {
                uint32_t b0, b1, b2, b3;
                uint32_t bo = (uint32_t)(j2 * 16 * 80 + kk * 32);
                ldm_x4(b_base + bo, b0, b1, b2, b3);
#pragma unroll
                for (int i = 0; i < 4; i++) {
                    float* d0 = acc[i][2 * j2];
                    float* d1 = acc[i][2 * j2 + 1];
                    mma_f16(d0[0], d0[1], d0[2], d0[3],
                            av[i][0], av[i][1], av[i][2], av[i][3], b0, b1);
                    mma_f16(d1[0], d1[1], d1[2], d1[3],
                            av[i][0], av[i][1], av[i][2], av[i][3], b2, b3);
                }
            }
        }
    }

    // head index for this warp's 64-col span (64-col spans never cross a head boundary)
    const int head = (nbase >> 7) + (warp_n >> 1);

    // epilogue: write fp16 h1 + fused alpha partials
#pragma unroll
    for (int i = 0; i < 4; i++) {
        int row0 = block_row + warp_m * 64 + i * 16 + (lane >> 2);
        float ps0 = 0.f, pd0 = 0.f, ps1 = 0.f, pd1 = 0.f;
#pragma unroll
        for (int j = 0; j < 8; j++) {
            int col = nbase + warp_n * 64 + j * 8 + (lane & 3) * 2;
            if (row0 < NN)
                *(uint32_t*)(g_h1h + (size_t)row0 * D1 + col) = pack_h2(acc[i][j][0], acc[i][j][1]);
            if (row0 + 8 < NN)
                *(uint32_t*)(g_h1h + (size_t)(row0 + 8) * D1 + col) = pack_h2(acc[i][j][2], acc[i][j][3]);
            float as0 = a_s[col], as1 = a_s[col + 1];
            float ad0 = a_d[col], ad1 = a_d[col + 1];
            ps0 = fmaf(acc[i][j][0], as0, ps0); ps0 = fmaf(acc[i][j][1], as1, ps0);
            pd0 = fmaf(acc[i][j][0], ad0, pd0); pd0 = fmaf(acc[i][j][1], ad1, pd0);
            ps1 = fmaf(acc[i][j][2], as0, ps1); ps1 = fmaf(acc[i][j][3], as1, ps1);
            pd1 = fmaf(acc[i][j][2], ad0, pd1); pd1 = fmaf(acc[i][j][3], ad1, pd1);
        }
        // reduce over the 4 lanes sharing a row (lane&3 group)
#pragma unroll
        for (int o = 1; o <= 2; o <<= 1) {
            ps0 += __shfl_xor_sync(0xffffffffu, ps0, o);
            pd0 += __shfl_xor_sync(0xffffffffu, pd0, o);
            ps1 += __shfl_xor_sync(0xffffffffu, ps1, o);
            pd1 += __shfl_xor_sync(0xffffffffu, pd1, o);
        }
        if ((lane & 3) == 0) {
            if (row0 < NN) {
                atomicAdd(&g_asrc1[row0 * H1 + head], ps0);
                atomicAdd(&g_adst1[row0 * H1 + head], pd0);
            }
            if (row0 + 8 < NN) {
                atomicAdd(&g_asrc1[(row0 + 8) * H1 + head], ps1);
                atomicAdd(&g_adst1[(row0 + 8) * H1 + head], pd1);
            }
        }
    }
}

// ==================== CSR build + zero ====================
__global__ void zero_kernel() {
    int i = blockIdx.x * blockDim.x + threadIdx.x;
    if (i < NN) g_deg[i] = 0;
    if (i < NN * H1) {
        g_asrc1[i] = 0.f;
        g_adst1[i] = 0.f;
    }
}

__global__ void count_kernel(const int* __restrict__ ei) {
    int e = blockIdx.x * blockDim.x + threadIdx.x;
    if (e >= ETOT) return;
    int dst = (e < EE) ? ei[EE + e] : (e - EE);
    atomicAdd(&g_deg[dst], 1);
}

__global__ __launch_bounds__(1024) void scan_kernel() {
    __shared__ int part[1024];
    const int t = threadIdx.x;
    const int CH = (NN + 1023) / 1024;
    const int base = t * CH;
    int s = 0;
    for (int i = 0; i < CH; i++) {
        int idx = base + i;
        if (idx < NN) s += g_deg[idx];
    }
    part[t] = s;
    __syncthreads();
    for (int o = 1; o < 1024; o <<= 1) {
        int v = (t >= o) ? part[t - o] : 0;
        __syncthreads();
        part[t] += v;
        __syncthreads();
    }
    int run = part[t] - s;
    for (int i = 0; i < CH; i++) {
        int idx = base + i;
        if (idx < NN) {
            g_off[idx] = run;
            g_cur[idx] = run;
            run += g_deg[idx];
        }
    }
    if (t == 1023) g_off[NN] = part[1023];
}

__global__ void scatter_kernel(const int* __restrict__ ei) {
    int e = blockIdx.x * blockDim.x + threadIdx.x;
    if (e >= ETOT) return;
    int src, dst;
    if (e < EE) { src = ei[e]; dst = ei[EE + e]; }
    else        { src = e - EE; dst = e - EE; }
    int pos = atomicAdd(&g_cur[dst], 1);
    g_srcs[pos] = src;
}

// ==================== Layer 1 softmax + aggregate + ELU ====================
__global__ __launch_bounds__(128) void agg1_kernel(const float* __restrict__ b1) {
    const int n = blockIdx.x;
    const int t = threadIdx.x;
    const int h = t >> 5;
    const int lane = t & 31;
    const int s0 = g_off[n];
    const int deg = g_off[n + 1] - s0;

    __shared__ float adsts[H1];
    __shared__ float sm[H1];
    __shared__ float sinv[H1];
    __shared__ float wm[4][H1];   // per-warp partial max
    __shared__ float ws[4][H1];   // per-warp partial sum
    __shared__ int   ssrc[128];
    __shared__ float scoef[128 * H1];

    if (t < H1) adsts[t] = g_adst1[n * H1 + t];
    __syncthreads();

    const float4* asrc4 = (const float4*)g_asrc1;

    // single online pass: running (max, sum) per head
    float m[H1] = {NEGBIG, NEGBIG, NEGBIG, NEGBIG};
    float sacc[H1] = {0.f, 0.f, 0.f, 0.f};
    for (int i = t; i < deg; i += 128) {
        float4 as = asrc4[g_srcs[s0 + i]];
        float l[H1];
        l[0] = lrelu(as.x + adsts[0]);
        l[1] = lrelu(as.y + adsts[1]);
        l[2] = lrelu(as.z + adsts[2]);
        l[3] = lrelu(as.w + adsts[3]);
#pragma unroll
        for (int hh = 0; hh < H1; hh++) {
            float M = fmaxf(m[hh], l[hh]);
            sacc[hh] = sacc[hh] * expf(m[hh] - M) + expf(l[hh] - M);
            m[hh] = M;
        }
    }
    // warp tree-combine (max,sum) pairs
#pragma unroll
    for (int o = 16; o; o >>= 1) {
#pragma unroll
        for (int hh = 0; hh < H1; hh++) {
            float mo = __shfl_xor_sync(0xffffffffu, m[hh], o);
            float so = __shfl_xor_sync(0xffffffffu, sacc[hh], o);
            float M = fmaxf(m[hh], mo);
            sacc[hh] = sacc[hh] * expf(m[hh] - M) + so * expf(mo - M);
            m[hh] = M;
        }
    }
    if (lane == 0) {
#pragma unroll
        for (int hh = 0; hh < H1; hh++) { wm[h][hh] = m[hh]; ws[h][hh] = sacc[hh]; }
    }
    __syncthreads();
    if (t < H1) {
        float M = wm[0][t], S = ws[0][t];
#pragma unroll
        for (int w = 1; w < 4; w++) {
            float mo = wm[w][t], so = ws[w][t];
            float M2 = fmaxf(M, mo);
            S = S * expf(M - M2) + so * expf(mo - M2);
            M = M2;
        }
        sm[t] = M;
        sinv[t] = 1.0f / S;
    }
    __syncthreads();

    // aggregation: thread t owns channels [4t, 4t+4)
    float ax = 0.f, ay = 0.f, az = 0.f, aw = 0.f;
    for (int base = 0; base < deg; base += 128) {
        int cnt = min(128, deg - base);
        if (t < cnt) {
            int s = g_srcs[s0 + base + t];
            ssrc[t] = s;
            float4 as = asrc4[s];
            scoef[t * H1 + 0] = expf(lrelu(as.x + adsts[0]) - sm[0]) * sinv[0];
            scoef[t * H1 + 1] = expf(lrelu(as.y + adsts[1]) - sm[1]) * sinv[1];
            scoef[t * H1 + 2] = expf(lrelu(as.z + adsts[2]) - sm[2]) * sinv[2];
            scoef[t * H1 + 3] = expf(lrelu(as.w + adsts[3]) - sm[3]) * sinv[3];
        }
        __syncthreads();
        int i = 0;
        for (; i + 2 <= cnt; i += 2) {
            int sA = ssrc[i], sB = ssrc[i + 1];
            uint2 uA = *(const uint2*)(g_h1h + (size_t)sA * D1 + 4 * t);
            uint2 uB = *(const uint2*)(g_h1h + (size_t)sB * D1 + 4 * t);
            float2 a0 = __half22float2(*(__half2*)&uA.x);
            float2 a1 = __half22float2(*(__half2*)&uA.y);
            float2 b0 = __half22float2(*(__half2*)&uB.x);
            float2 b1 = __half22float2(*(__half2*)&uB.y);
            float cA = scoef[i * H1 + h];
            float cB = scoef[(i + 1) * H1 + h];
            ax = fmaf(cA, a0.x, ax); ay = fmaf(cA, a0.y, ay);
            az = fmaf(cA, a1.x, az); aw = fmaf(cA, a1.y, aw);
            ax = fmaf(cB, b0.x, ax); ay = fmaf(cB, b0.y, ay);
            az = fmaf(cB, b1.x, az); aw = fmaf(cB, b1.y, aw);
        }
        if (i < cnt) {
            uint2 u = *(const uint2*)(g_h1h + (size_t)ssrc[i] * D1 + 4 * t);
            float2 v0 = __half22float2(*(__half2*)&u.x);
            float2 v1 = __half22float2(*(__half2*)&u.y);
            float cf = scoef[i * H1 + h];
            ax = fmaf(cf, v0.x, ax); ay = fmaf(cf, v0.y, ay);
            az = fmaf(cf, v1.x, az); aw = fmaf(cf, v1.y, aw);
        }
        __syncthreads();
    }

    float4 bb = *(const float4*)(b1 + 4 * t);
    float4 o;
    o.x = ax + bb.x; o.x = o.x > 0.f ? o.x : expm1f(o.x);
    o.y = ay + bb.y; o.y = o.y > 0.f ? o.y : expm1f(o.y);
    o.z = az + bb.z; o.z = o.z > 0.f ? o.z : expm1f(o.z);
    o.w = aw + bb.w; o.w = o.w > 0.f ? o.w : expm1f(o.w);
    *(float4*)(g_out1 + (size_t)n * D1 + 4 * t) = o;
}

// ==================== Layer 2 ====================
__global__ __launch_bounds__(256) void gemm2_kernel(const float* __restrict__ W2) {
    __shared__ float w[D1 * CLS];
    int t = threadIdx.x;
    for (int i = t; i < D1 * CLS; i += 256) w[i] = W2[i];
    __syncthreads();
    int warp = blockIdx.x * 8 + (t >> 5);
    int lane = t & 31;
    if (warp >= NN) return;
    const float* row = g_out1 + (size_t)warp * D1;
    float acc[CLS] = {0.f, 0.f, 0.f, 0.f, 0.f, 0.f};
    for (int k = lane; k < D1; k += 32) {
        float v = row[k];
        const float* wr = &w[k * CLS];
#pragma unroll
        for (int c = 0; c < CLS; c++) acc[c] = fmaf(v, wr[c], acc[c]);
    }
#pragma unroll
    for (int o = 16; o; o >>= 1)
#pragma unroll
        for (int c = 0; c < CLS; c++) acc[c] += __shfl_xor_sync(0xffffffffu, acc[c], o);
    if (lane == 0) {
#pragma unroll
        for (int c = 0; c < CLS; c++) g_h2[warp * CLS + c] = acc[c];
    }
}

__global__ void alpha2_kernel(const float* __restrict__ a_s, const float* __restrict__ a_d) {
    int n = blockIdx.x * blockDim.x + threadIdx.x;
    if (n >= NN) return;
    float s = 0.f, d = 0.f;
#pragma unroll
    for (int c = 0; c < CLS; c++) {
        float v = g_h2[n * CLS + c];
        s = fmaf(v, a_s[c], s);
        d = fmaf(v, a_d[c], d);
    }
    g_as2[n] = s;
    g_ad2[n] = d;
}

__global__ __launch_bounds__(128) void agg2_kernel(const float* __restrict__ b2,
                                                   float* __restrict__ out) {
    int n = blockIdx.x * 4 + (threadIdx.x >> 5);
    int lane = threadIdx.x & 31;
    if (n >= NN) return;
    int s0 = g_off[n];
    int deg = g_off[n + 1] - s0;
    float ad = g_ad2[n];

    float lmax = -INFINITY;
    for (int i = lane; i < deg; i += 32) {
        int s = g_srcs[s0 + i];
        lmax = fmaxf(lmax, lrelu(g_as2[s] + ad));
    }
#pragma unroll
    for (int o = 16; o; o >>= 1) lmax = fmaxf(lmax, __shfl_xor_sync(0xffffffffu, lmax, o));

    float lsum = 0.f;
    for (int i = lane; i < deg; i += 32) {
        int s = g_srcs[s0 + i];
        lsum += expf(lrelu(g_as2[s] + ad) - lmax);
    }
#pragma unroll
    for (int o = 16; o; o >>= 1) lsum += __shfl_xor_sync(0xffffffffu, lsum, o);
    float inv = 1.0f / lsum;

    float acc[CLS] = {0.f, 0.f, 0.f, 0.f, 0.f, 0.f};
    for (int i = lane; i < deg; i += 32) {
        int s = g_srcs[s0 + i];
        float coef = expf(lrelu(g_as2[s] + ad) - lmax) * inv;
        const float* hp = g_h2 + s * CLS;
#pragma unroll
        for (int c = 0; c < CLS; c++) acc[c] = fmaf(coef, hp[c], acc[c]);
    }
#pragma unroll
    for (int o = 16; o; o >>= 1)
#pragma unroll
        for (int c = 0; c < CLS; c++) acc[c] += __shfl_xor_sync(0xffffffffu, acc[c], o);

    if (lane == 0) {
#pragma unroll
        for (int c = 0; c < CLS; c++) out[n * CLS + c] = acc[c] + b2[c];
    }
}

// ==================== Launch ====================
extern "C" void kernel_launch(void* const* d_in, const int* in_sizes, int n_in,
                              void* d_out, int out_size) {
    const float* x   = (const float*)d_in[0];
    const int*   ei  = (const int*)  d_in[1];
    const float* W1  = (const float*)d_in[2];
    const float* as1 = (const float*)d_in[3];
    const float* ad1 = (const float*)d_in[4];
    const float* b1  = (const float*)d_in[5];
    const float* W2  = (const float*)d_in[6];
    const float* as2 = (const float*)d_in[7];
    const float* ad2 = (const float*)d_in[8];
    const float* b2  = (const float*)d_in[9];
    float* out = (float*)d_out;

    static bool attr_set = false;
    if (!attr_set) {
        cudaFuncSetAttribute(mma1_kernel, cudaFuncAttributeMaxDynamicSharedMemorySize, SMEM_SZ);
        attr_set = true;
    }

    // zero degs + alpha accumulators; CSR build
    zero_kernel<<<(NN * H1 + 255) / 256, 256>>>();
    count_kernel<<<(ETOT + 255) / 256, 256>>>(ei);
    scan_kernel<<<1, 1024>>>();
    scatter_kernel<<<(ETOT + 255) / 256, 256>>>(ei);

    // W1 -> fp16 transposed
    convw1_kernel<<<dim3(D1 / 32, FIN / 32), 256>>>(W1);

    // Layer 1: GEMM + fused alpha1, then attention aggregate
    mma1_kernel<<<dim3(D1 / 256, (NN + 127) / 128), 256, SMEM_SZ>>>(x, as1, ad1);
    agg1_kernel<<<NN, 128>>>(b1);

    // Layer 2
    gemm2_kernel<<<(NN + 7) / 8, 256>>>(W2);
    alpha2_kernel<<<(NN + 255) / 256, 256>>>(as2, ad2);
    agg2_kernel<<<(NN + 3) / 4, 128>>>(b2, out);
}